// round 6
// baseline (speedup 1.0000x reference)
#include <cuda_runtime.h>
#include <cuda_bf16.h>

// InterAgg (FRAUDRE inter-relation aggregation), GB300 sm_103a.
//
// out[n] = [ self | relu(self) | sum_r relu(mean_j feat[nidx_r[n,j]]) * softmax(alpha)[64:,r] ]
// (softmax rows sum to 1 => aggregated first half == relu(self) exactly)
//
// R3: LDG.128 gathers — each warp instruction loads TWO neighbor rows
// (lanes 0-15 = row j, lanes 16-31 = row j+1, float4 per lane, 512B/request).
// Halves the gather request count vs the LDG.64 scheme; both prior configs
// were pinned at 5.2TB/s with no saturated unit => request-rate limited.

#define NB 8192
#define DEG 32

__device__ __forceinline__ void softmax3(float& a, float& b, float& c) {
    float m = fmaxf(a, fmaxf(b, c));
    float e0 = __expf(a - m);
    float e1 = __expf(b - m);
    float e2 = __expf(c - m);
    float inv = __frcp_rn(e0 + e1 + e2);
    a = e0 * inv; b = e1 * inv; c = e2 * inv;
}

__global__ __launch_bounds__(256, 4)
void interagg_kernel(const float4* __restrict__ feat4,   // features as float4[NUM_NODES*16]
                     const float*  __restrict__ alpha,   // (128, 3)
                     const int*    __restrict__ nodes,   // (NB,)
                     const int*    __restrict__ n1,      // (NB, DEG)
                     const int*    __restrict__ n2,
                     const int*    __restrict__ n3,
                     float*        __restrict__ out)     // (NB, 192)
{
    const int w    = (blockIdx.x * blockDim.x + threadIdx.x) >> 5;
    const int lane = threadIdx.x & 31;
    if (w >= NB) return;

    const int half = lane >> 4;      // 0: even j rows, 1: odd j rows
    const int sl   = lane & 15;      // lane owns dims 4sl..4sl+3

    // --- index loads (coalesced; lane j owns neighbor j) ---
    const int node = __ldg(&nodes[w]);
    const int base = w * DEG + lane;
    const int i1 = __ldg(&n1[base]);
    const int i2 = __ldg(&n2[base]);
    const int i3 = __ldg(&n3[base]);

    // --- self row (both halves load same 256B row; L2 broadcast-dedups) ---
    const float4 s = __ldg(&feat4[node * 16 + sl]);

    float4 a1 = make_float4(0.f, 0.f, 0.f, 0.f);
    float4 a2 = make_float4(0.f, 0.f, 0.f, 0.f);
    float4 a3 = make_float4(0.f, 0.f, 0.f, 0.f);

    // --- gathers: each LDG.128 warp-instruction covers 2 neighbor rows ---
#pragma unroll
    for (int j = 0; j < DEG; j += 4) {
        const int jA = j + half;
        const int jB = j + 2 + half;
        const int x1A = __shfl_sync(0xffffffffu, i1, jA);
        const int x1B = __shfl_sync(0xffffffffu, i1, jB);
        const int x2A = __shfl_sync(0xffffffffu, i2, jA);
        const int x2B = __shfl_sync(0xffffffffu, i2, jB);
        const int x3A = __shfl_sync(0xffffffffu, i3, jA);
        const int x3B = __shfl_sync(0xffffffffu, i3, jB);

        const float4 v1A = __ldg(&feat4[x1A * 16 + sl]);
        const float4 v1B = __ldg(&feat4[x1B * 16 + sl]);
        const float4 v2A = __ldg(&feat4[x2A * 16 + sl]);
        const float4 v2B = __ldg(&feat4[x2B * 16 + sl]);
        const float4 v3A = __ldg(&feat4[x3A * 16 + sl]);
        const float4 v3B = __ldg(&feat4[x3B * 16 + sl]);

        a1.x += v1A.x + v1B.x;  a1.y += v1A.y + v1B.y;
        a1.z += v1A.z + v1B.z;  a1.w += v1A.w + v1B.w;
        a2.x += v2A.x + v2B.x;  a2.y += v2A.y + v2B.y;
        a2.z += v2A.z + v2B.z;  a2.w += v2A.w + v2B.w;
        a3.x += v3A.x + v3B.x;  a3.y += v3A.y + v3B.y;
        a3.z += v3A.z + v3B.z;  a3.w += v3A.w + v3B.w;
    }

    // --- fold the two j-parity halves (lane l <-> l^16 hold same dims) ---
#pragma unroll
    for (int k = 0; k < 1; k++) {
        a1.x += __shfl_xor_sync(0xffffffffu, a1.x, 16);
        a1.y += __shfl_xor_sync(0xffffffffu, a1.y, 16);
        a1.z += __shfl_xor_sync(0xffffffffu, a1.z, 16);
        a1.w += __shfl_xor_sync(0xffffffffu, a1.w, 16);
        a2.x += __shfl_xor_sync(0xffffffffu, a2.x, 16);
        a2.y += __shfl_xor_sync(0xffffffffu, a2.y, 16);
        a2.z += __shfl_xor_sync(0xffffffffu, a2.z, 16);
        a2.w += __shfl_xor_sync(0xffffffffu, a2.w, 16);
        a3.x += __shfl_xor_sync(0xffffffffu, a3.x, 16);
        a3.y += __shfl_xor_sync(0xffffffffu, a3.y, 16);
        a3.z += __shfl_xor_sync(0xffffffffu, a3.z, 16);
        a3.w += __shfl_xor_sync(0xffffffffu, a3.w, 16);
    }

    // --- per-dim softmax weights for agg dims 4sl..4sl+3 (alpha rows 64+..) ---
    const int r0 = (64 + 4 * sl) * 3;
    float w00 = __ldg(&alpha[r0 + 0]),  w01 = __ldg(&alpha[r0 + 1]),  w02 = __ldg(&alpha[r0 + 2]);
    float w10 = __ldg(&alpha[r0 + 3]),  w11 = __ldg(&alpha[r0 + 4]),  w12 = __ldg(&alpha[r0 + 5]);
    float w20 = __ldg(&alpha[r0 + 6]),  w21 = __ldg(&alpha[r0 + 7]),  w22 = __ldg(&alpha[r0 + 8]);
    float w30 = __ldg(&alpha[r0 + 9]),  w31 = __ldg(&alpha[r0 + 10]), w32 = __ldg(&alpha[r0 + 11]);
    softmax3(w00, w01, w02);
    softmax3(w10, w11, w12);
    softmax3(w20, w21, w22);
    softmax3(w30, w31, w32);

    const float inv = 1.0f / (float)DEG;
    const float g1x = fmaxf(a1.x * inv, 0.f), g1y = fmaxf(a1.y * inv, 0.f);
    const float g1z = fmaxf(a1.z * inv, 0.f), g1w = fmaxf(a1.w * inv, 0.f);
    const float g2x = fmaxf(a2.x * inv, 0.f), g2y = fmaxf(a2.y * inv, 0.f);
    const float g2z = fmaxf(a2.z * inv, 0.f), g2w = fmaxf(a2.w * inv, 0.f);
    const float g3x = fmaxf(a3.x * inv, 0.f), g3y = fmaxf(a3.y * inv, 0.f);
    const float g3z = fmaxf(a3.z * inv, 0.f), g3w = fmaxf(a3.w * inv, 0.f);

    float4 o;
    o.x = g1x * w00 + g2x * w01 + g3x * w02;
    o.y = g1y * w10 + g2y * w11 + g3y * w12;
    o.z = g1z * w20 + g2z * w21 + g3z * w22;
    o.w = g1w * w30 + g2w * w31 + g3w * w32;

    float4 rs = make_float4(fmaxf(s.x, 0.f), fmaxf(s.y, 0.f),
                            fmaxf(s.z, 0.f), fmaxf(s.w, 0.f));

    // --- write 192 floats = 48 float4: [self | relu(self) | weighted agg] ---
    float4* ob = reinterpret_cast<float4*>(out + (size_t)w * 192);
    if (half == 0) {
        ob[sl]      = s;    // self
        ob[32 + sl] = o;    // weighted agg
    } else {
        ob[16 + sl] = rs;   // relu(self)
    }
}

extern "C" void kernel_launch(void* const* d_in, const int* in_sizes, int n_in,
                              void* d_out, int out_size) {
    const float4* feat4 = (const float4*)d_in[0];
    const float*  alpha = (const float*)d_in[1];
    const int*    nodes = (const int*)d_in[2];
    const int*    n1    = (const int*)d_in[3];
    const int*    n2    = (const int*)d_in[4];
    const int*    n3    = (const int*)d_in[5];
    float*        out   = (float*)d_out;

    const int threads = 256;   // 8 warps = 8 nodes / block
    const int blocks  = (NB * 32 + threads - 1) / threads;  // 1024
    interagg_kernel<<<blocks, threads>>>(feat4, alpha, nodes, n1, n2, n3, out);
}